// round 8
// baseline (speedup 1.0000x reference)
#include <cuda_runtime.h>
#include <math.h>
#include <stdint.h>

#define BB   256
#define TT   1000
#define NIN  128
#define UNITS 512

// scratch: precomputed input currents i_in[b][t][u]; diag-zeroed W_rec
__device__ float g_iin[(size_t)BB * TT * UNITS];
__device__ float g_wrec[(size_t)UNITS * UNITS];

// ---------------------------------------------------------------------------
// Prep: copy W_rec with diagonal zeroed (reference zeroes diag BEFORE matmul;
// a zero contributes fma(z,0,acc)=acc exactly inside any chain).
// ---------------------------------------------------------------------------
__global__ void prep_wrec_kernel(const float* __restrict__ W_rec) {
    int idx = blockIdx.x * blockDim.x + threadIdx.x;   // 0..262143
    int row = idx >> 9, col = idx & 511;
    g_wrec[idx] = (row == col) ? 0.0f : W_rec[idx];
}

// ---------------------------------------------------------------------------
// Phase 1: i_in = X @ W_in  (M=B*T=256000, K=128, N=512), pure fp32.
// Serial ascending-k FMA chain, single accumulator — matches cuBLAS/Triton
// large-gemm accumulation bit-exactly (chunking does not alter a serial chain).
// ---------------------------------------------------------------------------
#define GTM 128
#define GTN 128
#define GTK 32

__global__ __launch_bounds__(256) void gemm_kernel(const float* __restrict__ X,
                                                   const float* __restrict__ Wm) {
    __shared__ float As[GTK][GTM + 4];
    __shared__ float Bs[GTK][GTN];
    const int bm = blockIdx.y * GTM;
    const int bn = blockIdx.x * GTN;
    const int tid = threadIdx.x;
    const int tx = tid & 15, ty = tid >> 4;

    float acc[8][8] = {};

    for (int kc = 0; kc < NIN; kc += GTK) {
        #pragma unroll
        for (int i = 0; i < 4; i++) {
            int idx = tid + i * 256;
            int m  = idx >> 3;
            int k4 = idx & 7;
            float4 vv = *(const float4*)(X + (size_t)(bm + m) * NIN + kc + k4 * 4);
            As[k4 * 4 + 0][m] = vv.x;
            As[k4 * 4 + 1][m] = vv.y;
            As[k4 * 4 + 2][m] = vv.z;
            As[k4 * 4 + 3][m] = vv.w;
        }
        #pragma unroll
        for (int i = 0; i < 4; i++) {
            int idx = tid + i * 256;
            int k  = idx >> 5;
            int n4 = idx & 31;
            *(float4*)(&Bs[k][n4 * 4]) =
                *(const float4*)(Wm + (size_t)(kc + k) * UNITS + bn + n4 * 4);
        }
        __syncthreads();

        #pragma unroll
        for (int k = 0; k < GTK; k++) {        // ascending k
            float a[8], b[8];
            *(float4*)(a)     = *(const float4*)(&As[k][ty * 8]);
            *(float4*)(a + 4) = *(const float4*)(&As[k][ty * 8 + 4]);
            *(float4*)(b)     = *(const float4*)(&Bs[k][tx * 8]);
            *(float4*)(b + 4) = *(const float4*)(&Bs[k][tx * 8 + 4]);
            #pragma unroll
            for (int i = 0; i < 8; i++)
                #pragma unroll
                for (int j = 0; j < 8; j++)
                    acc[i][j] = fmaf(a[i], b[j], acc[i][j]);
        }
        __syncthreads();
    }

    #pragma unroll
    for (int i = 0; i < 8; i++) {
        float* crow = g_iin + (size_t)(bm + ty * 8 + i) * UNITS + bn + tx * 8;
        __stcs((float4*)(crow),     *(float4*)(&acc[i][0]));
        __stcs((float4*)(crow + 4), *(float4*)(&acc[i][4]));
    }
}

// ---------------------------------------------------------------------------
// Phase 2: ALIF scan, one CTA per batch (256 CTAs x 512 threads, thread=unit).
// rec = z @ W_rec emulating cuBLAS sgemm_*_sliced1x4: per 32-deep K chunk the
// 4 slices take 8-contiguous k each (slice s owns byte s of each 32-bit mask
// word); partial p_s = sum over its k's ascending (sparse skip is bit-exact);
// combined serially ((p0+p1)+p2)+p3; then i_in added after (beta-fold order,
// commutes bit-exactly).
// Step math: contracted tree (XLA GPU LLVM FMA contraction, left-mul fused).
// ---------------------------------------------------------------------------
__global__ __launch_bounds__(512) void scan_kernel(float* __restrict__ out,
                                                   float decay, float omd,
                                                   float decay_b, float omdb) {
    __shared__ unsigned s_mask[16];

    const int u    = threadIdx.x;
    const int b    = blockIdx.x;
    const int warp = u >> 5;
    const int lane = u & 31;

    if (u < 16) s_mask[u] = 0u;
    __syncthreads();

    float v = 0.f, bad = 0.f, zprev = 0.f;

    const float* iptr = g_iin + (size_t)b * TT * UNITS + u;
    float*       optr = out   + (size_t)b * TT * UNITS + u;

    for (int t = 0; t < TT; t++) {
        float inp = __ldcs(iptr + (size_t)t * UNITS);

        // sliced1x4 byte-interleaved partials: slice s <- byte s of each word
        float p0 = 0.f, p1 = 0.f, p2 = 0.f, p3 = 0.f;
        #pragma unroll
        for (int w = 0; w < 16; w++) {
            unsigned m = s_mask[w];
            const char* base = (const char*)(g_wrec + (size_t)(w << 5) * UNITS + u);
            unsigned b0 =  m        & 0xFFu;           // k local 0..7
            while (b0) { int j = __ffs(b0) - 1; b0 &= b0 - 1;
                p0 = __fadd_rn(p0, *(const float*)(base + ((size_t)j        << 11))); }
            unsigned b1 = (m >> 8)  & 0xFFu;           // k local 8..15
            while (b1) { int j = __ffs(b1) - 1; b1 &= b1 - 1;
                p1 = __fadd_rn(p1, *(const float*)(base + ((size_t)(8 + j)  << 11))); }
            unsigned b2 = (m >> 16) & 0xFFu;           // k local 16..23
            while (b2) { int j = __ffs(b2) - 1; b2 &= b2 - 1;
                p2 = __fadd_rn(p2, *(const float*)(base + ((size_t)(16 + j) << 11))); }
            unsigned b3 = (m >> 24) & 0xFFu;           // k local 24..31
            while (b3) { int j = __ffs(b3) - 1; b3 &= b3 - 1;
                p3 = __fadd_rn(p3, *(const float*)(base + ((size_t)(24 + j) << 11))); }
        }
        float rec = __fadd_rn(__fadd_rn(__fadd_rn(p0, p1), p2), p3);

        // contracted step tree (LLVM fmad: left fmul of each fadd fused):
        float nb  = fmaf(decay_b, bad, __fmul_rn(omdb, zprev));
        float thr = fmaf(nb, 1.6f, 0.01f);
        float it  = __fadd_rn(inp, rec);                  // == rn(rec+inp), exact
        float nv  = fmaf(-zprev, thr, fmaf(decay, v, __fmul_rn(omd, it)));
        float z   = (nv > thr) ? 1.0f : 0.0f;             // (nv-thr)/thr>0 iff nv>thr

        v = nv; bad = nb; zprev = z;
        __stcs(optr + (size_t)t * UNITS, z);

        __syncthreads();                                   // reads of old mask done
        unsigned bal = __ballot_sync(0xffffffffu, z != 0.f);
        if (lane == 0) s_mask[warp] = bal;
        __syncthreads();                                   // new mask visible
    }
}

// ---------------------------------------------------------------------------
extern "C" void kernel_launch(void* const* d_in, const int* in_sizes, int n_in,
                              void* d_out, int out_size) {
    const float* x     = (const float*)d_in[0];   // [B, T, N_IN]
    const float* W_in  = (const float*)d_in[1];   // [N_IN, UNITS]
    const float* W_rec = (const float*)d_in[2];   // [UNITS, UNITS]
    float* out = (float*)d_out;                   // [B, T, UNITS]

    (void)in_sizes; (void)n_in; (void)out_size;

    // correctly-rounded fp32 constants (verified safe margins to rounding ties;
    // 1-x exact by Sterbenz)
    float decay   = (float)exp(-1.0 / 20.0);
    float decay_b = (float)exp(-1.0 / 200.0);
    float omd     = 1.0f - decay;
    float omdb    = 1.0f - decay_b;

    prep_wrec_kernel<<<256, 1024>>>(W_rec);

    dim3 ggrid(UNITS / GTN, (BB * TT) / GTM);     // (4, 2000)
    gemm_kernel<<<ggrid, 256>>>(x, W_in);

    scan_kernel<<<BB, 512>>>(out, decay, omd, decay_b, omdb);
}

// round 9
// speedup vs baseline: 1.5901x; 1.5901x over previous
#include <cuda_runtime.h>
#include <math.h>
#include <stdint.h>

#define BB   256
#define TT   1000
#define NIN  128
#define UNITS 512

// scratch: precomputed input currents i_in[b][t][u]; diag-zeroed W_rec
__device__ float g_iin[(size_t)BB * TT * UNITS];
__device__ float g_wrec[(size_t)UNITS * UNITS];

// ---------------------------------------------------------------------------
// Prep: copy W_rec with diagonal zeroed (reference zeroes diag BEFORE matmul).
// ---------------------------------------------------------------------------
__global__ void prep_wrec_kernel(const float* __restrict__ W_rec) {
    int idx = blockIdx.x * blockDim.x + threadIdx.x;   // 0..262143
    int row = idx >> 9, col = idx & 511;
    g_wrec[idx] = (row == col) ? 0.0f : W_rec[idx];
}

// ---------------------------------------------------------------------------
// Phase 1: i_in = X @ W_in  (M=B*T=256000, K=128, N=512), pure fp32 serial
// ascending-k FMA chain (bit-matches the reference GEMM). ~0.6ms, near peak.
// ---------------------------------------------------------------------------
#define GTM 128
#define GTN 128
#define GTK 32

__global__ __launch_bounds__(256) void gemm_kernel(const float* __restrict__ X,
                                                   const float* __restrict__ Wm) {
    __shared__ float As[GTK][GTM + 4];
    __shared__ float Bs[GTK][GTN];
    const int bm = blockIdx.y * GTM;
    const int bn = blockIdx.x * GTN;
    const int tid = threadIdx.x;
    const int tx = tid & 15, ty = tid >> 4;

    float acc[8][8] = {};

    for (int kc = 0; kc < NIN; kc += GTK) {
        #pragma unroll
        for (int i = 0; i < 4; i++) {
            int idx = tid + i * 256;
            int m  = idx >> 3;
            int k4 = idx & 7;
            float4 vv = *(const float4*)(X + (size_t)(bm + m) * NIN + kc + k4 * 4);
            As[k4 * 4 + 0][m] = vv.x;
            As[k4 * 4 + 1][m] = vv.y;
            As[k4 * 4 + 2][m] = vv.z;
            As[k4 * 4 + 3][m] = vv.w;
        }
        #pragma unroll
        for (int i = 0; i < 4; i++) {
            int idx = tid + i * 256;
            int k  = idx >> 5;
            int n4 = idx & 31;
            *(float4*)(&Bs[k][n4 * 4]) =
                *(const float4*)(Wm + (size_t)(kc + k) * UNITS + bn + n4 * 4);
        }
        __syncthreads();

        #pragma unroll
        for (int k = 0; k < GTK; k++) {
            float a[8], b[8];
            *(float4*)(a)     = *(const float4*)(&As[k][ty * 8]);
            *(float4*)(a + 4) = *(const float4*)(&As[k][ty * 8 + 4]);
            *(float4*)(b)     = *(const float4*)(&Bs[k][tx * 8]);
            *(float4*)(b + 4) = *(const float4*)(&Bs[k][tx * 8 + 4]);
            #pragma unroll
            for (int i = 0; i < 8; i++)
                #pragma unroll
                for (int j = 0; j < 8; j++)
                    acc[i][j] = fmaf(a[i], b[j], acc[i][j]);
        }
        __syncthreads();
    }

    #pragma unroll
    for (int i = 0; i < 8; i++) {
        float* crow = g_iin + (size_t)(bm + ty * 8 + i) * UNITS + bn + tx * 8;
        __stcs((float4*)(crow),     *(float4*)(&acc[i][0]));
        __stcs((float4*)(crow + 4), *(float4*)(&acc[i][4]));
    }
}

// ---------------------------------------------------------------------------
// Phase 2: ALIF scan — arithmetic FROZEN from the passing R8 kernel
// (sliced1x4 byte-interleave: slice s owns byte s of each 32-bit mask word;
// per-slice ascending (word,bit) fadd chain; ((p0+p1)+p2)+p3; contracted
// step tree). This round only restructures the SCHEDULE: per-step index-list
// compaction (order-preserving) so the weight loads run at MLP>=4 instead of
// a serial load->add chain.
// ---------------------------------------------------------------------------
__global__ __launch_bounds__(512) void scan_kernel(float* __restrict__ out,
                                                   float decay, float omd,
                                                   float decay_b, float omdb) {
    __shared__ unsigned        s_mask[2][16];
    __shared__ unsigned short  s_idx[2][4][136];   // per-slice active-k lists
    __shared__ int             s_cnt[2][4];

    const int u    = threadIdx.x;
    const int b    = blockIdx.x;
    const int warp = u >> 5;
    const int lane = u & 31;

    if (u < 16) { s_mask[0][u] = 0u; s_mask[1][u] = 0u; }
    if (u < 8)  s_cnt[u >> 2][u & 3] = 0;
    __syncthreads();

    float v = 0.f, bad = 0.f, zprev = 0.f;

    const float* col  = g_wrec + u;                       // column u of W_rec
    const float* iptr = g_iin + (size_t)b * TT * UNITS + u;
    float*       optr = out   + (size_t)b * TT * UNITS + u;

    for (int t = 0; t < TT; t++) {
        const int buf = t & 1;
        float inp = __ldcs(iptr + (size_t)t * UNITS);

        // ---- compaction: warp s (s<4) builds slice-s index list in the
        // exact ascending (word, bit-in-byte) order of the frozen sum ----
        if (warp < 4) {
            unsigned byte = (lane < 16)
                          ? ((s_mask[buf][lane] >> (warp * 8)) & 0xFFu) : 0u;
            int c  = __popc(byte);
            int sc = c;
            #pragma unroll
            for (int off = 1; off < 32; off <<= 1) {
                int nbr = __shfl_up_sync(0xffffffffu, sc, off);
                if (lane >= off) sc += nbr;
            }
            int pos = sc - c;                      // exclusive prefix
            unsigned mm = byte;
            while (mm) {
                int j = __ffs(mm) - 1; mm &= mm - 1;
                s_idx[buf][warp][pos++] =
                    (unsigned short)(lane * 32 + warp * 8 + j);
            }
            if (lane == 15) s_cnt[buf][warp] = sc; // total actives in slice
        }
        __syncthreads();                           // lists visible to all

        // ---- sparse sums, MLP-unrolled; identical fadd order per slice ----
        float p[4];
        #pragma unroll
        for (int s = 0; s < 4; s++) {
            const int n = s_cnt[buf][s];
            const unsigned short* il = s_idx[buf][s];
            float acc = 0.f;
            int i = 0;
            for (; i + 8 <= n; i += 8) {
                float v0 = col[(size_t)il[i]     * UNITS];
                float v1 = col[(size_t)il[i + 1] * UNITS];
                float v2 = col[(size_t)il[i + 2] * UNITS];
                float v3 = col[(size_t)il[i + 3] * UNITS];
                float v4 = col[(size_t)il[i + 4] * UNITS];
                float v5 = col[(size_t)il[i + 5] * UNITS];
                float v6 = col[(size_t)il[i + 6] * UNITS];
                float v7 = col[(size_t)il[i + 7] * UNITS];
                acc = __fadd_rn(acc, v0); acc = __fadd_rn(acc, v1);
                acc = __fadd_rn(acc, v2); acc = __fadd_rn(acc, v3);
                acc = __fadd_rn(acc, v4); acc = __fadd_rn(acc, v5);
                acc = __fadd_rn(acc, v6); acc = __fadd_rn(acc, v7);
            }
            if (i + 4 <= n) {
                float v0 = col[(size_t)il[i]     * UNITS];
                float v1 = col[(size_t)il[i + 1] * UNITS];
                float v2 = col[(size_t)il[i + 2] * UNITS];
                float v3 = col[(size_t)il[i + 3] * UNITS];
                acc = __fadd_rn(acc, v0); acc = __fadd_rn(acc, v1);
                acc = __fadd_rn(acc, v2); acc = __fadd_rn(acc, v3);
                i += 4;
            }
            for (; i < n; i++)
                acc = __fadd_rn(acc, col[(size_t)il[i] * UNITS]);
            p[s] = acc;
        }
        float rec = __fadd_rn(__fadd_rn(__fadd_rn(p[0], p[1]), p[2]), p[3]);

        // ---- frozen contracted step tree ----
        float nb  = fmaf(decay_b, bad, __fmul_rn(omdb, zprev));
        float thr = fmaf(nb, 1.6f, 0.01f);
        float it  = __fadd_rn(inp, rec);
        float nv  = fmaf(-zprev, thr, fmaf(decay, v, __fmul_rn(omd, it)));
        float z   = (nv > thr) ? 1.0f : 0.0f;

        v = nv; bad = nb; zprev = z;
        __stcs(optr + (size_t)t * UNITS, z);

        // publish next-step mask into the other buffer (no WAR hazards)
        unsigned bal = __ballot_sync(0xffffffffu, z != 0.f);
        if (lane == 0) s_mask[buf ^ 1][warp] = bal;
        __syncthreads();                            // mask visible for t+1
    }
}

// ---------------------------------------------------------------------------
extern "C" void kernel_launch(void* const* d_in, const int* in_sizes, int n_in,
                              void* d_out, int out_size) {
    const float* x     = (const float*)d_in[0];   // [B, T, N_IN]
    const float* W_in  = (const float*)d_in[1];   // [N_IN, UNITS]
    const float* W_rec = (const float*)d_in[2];   // [UNITS, UNITS]
    float* out = (float*)d_out;                   // [B, T, UNITS]

    (void)in_sizes; (void)n_in; (void)out_size;

    // correctly-rounded fp32 constants (frozen)
    float decay   = (float)exp(-1.0 / 20.0);
    float decay_b = (float)exp(-1.0 / 200.0);
    float omd     = 1.0f - decay;
    float omdb    = 1.0f - decay_b;

    prep_wrec_kernel<<<256, 1024>>>(W_rec);

    dim3 ggrid(UNITS / GTN, (BB * TT) / GTM);     // (4, 2000)
    gemm_kernel<<<ggrid, 256>>>(x, W_in);

    scan_kernel<<<BB, 512>>>(out, decay, omd, decay_b, omdb);
}